// round 6
// baseline (speedup 1.0000x reference)
#include <cuda_runtime.h>
#include <cstdint>

#define NEGF (-1e30f)
#define EPSF (1e-7f)
#define LN2F (0.69314718055994531f)

constexpr int Bc = 64;
constexpr int Tc = 1024;
constexpr int Cc = 128;
constexpr int Lc = 256;
constexpr int BLANKc = Cc - 1;    // 127
constexpr int NPW  = 4;           // producer warps (wid 0..3)
constexpr int NCW  = 8;           // consumer warps (wid 4..11), pair p = cw*32+lane
constexpr int NT   = (NPW + NCW) * 32;   // 384
constexpr int RING = 80;          // lp row ring (80*512B = 40KB)
constexpr int BRING = 64;         // boundary ring per warp-pair

__device__ __forceinline__ float ex2f_(float x){ float r; asm("ex2.approx.ftz.f32 %0, %1;" : "=f"(r) : "f"(x)); return r; }
__device__ __forceinline__ float lg2f_(float x){ float r; asm("lg2.approx.f32 %0, %1;"    : "=f"(r) : "f"(x)); return r; }

__device__ __forceinline__ float lse2f(float a, float b){
    float m = fmaxf(a, b), l = fminf(a, b);
    return m + lg2f_(1.0f + ex2f_(l - m));
}
__device__ __forceinline__ float lse3f(float x, float y, float z){
    float hi = fmaxf(x, y), lo = fminf(x, y);
    float m  = fmaxf(hi, z), t1 = fminf(hi, z);
    float mid = fmaxf(t1, lo), low = fminf(t1, lo);
    return m + lg2f_(1.0f + ex2f_(mid - m) + ex2f_(low - m));
}

__device__ __forceinline__ unsigned su32(const void* p){ return (unsigned)__cvta_generic_to_shared(p); }
__device__ __forceinline__ void   stsv64(unsigned a, float x, float y){
    asm volatile("st.volatile.shared.v2.f32 [%0], {%1,%2};" :: "r"(a), "f"(x), "f"(y)); }
__device__ __forceinline__ float2 ldsv64(unsigned a){
    float2 r; asm volatile("ld.volatile.shared.v2.f32 {%0,%1}, [%2];" : "=f"(r.x), "=f"(r.y) : "r"(a)); return r; }
__device__ __forceinline__ void   stsv32i(unsigned a, int v){
    asm volatile("st.volatile.shared.s32 [%0], %1;" :: "r"(a), "r"(v)); }
__device__ __forceinline__ int    ldsv32i(unsigned a){
    int r; asm volatile("ld.volatile.shared.s32 %0, [%1];" : "=r"(r) : "r"(a)); return r; }

__global__ __launch_bounds__(NT, 1) void ctc_loss_kernel(
    const int*   __restrict__ y_true,        // (B, L)
    const float* __restrict__ y_pred,        // (B, T, C)
    const int*   __restrict__ input_length,  // (B, 1)
    const int*   __restrict__ label_length,  // (B, 1)
    float*       __restrict__ out)           // (B, 1)
{
    __shared__ float  lp[RING][Cc];                 // log2(p+EPS) row ring
    __shared__ float2 bnd[NCW - 1][BRING];          // (a1, seq) boundary rings
    __shared__ int    prog[NCW];                    // consumer progress (volatile access)
    __shared__ int    pstage[NPW];                  // producer staged-row progress
    __shared__ float  res2[2];

    const int b    = blockIdx.x;
    const int tid  = threadIdx.x;
    const int wid  = tid >> 5;
    const int lane = tid & 31;
    const float* __restrict__ yp = y_pred + (size_t)b * Tc * Cc;
    const int*   __restrict__ yt = y_true + b * Lc;
    const int inLen  = input_length[b];
    const int labLen = label_length[b];
    const int Sval   = 2 * labLen + 1;

    // ---- shared init ----
    if (tid == 0) {
        #pragma unroll
        for (int i = 0; i < NCW; ++i) prog[i] = 0;
        #pragma unroll
        for (int i = 0; i < NPW; ++i) pstage[i] = 0;
        res2[0] = NEGF; res2[1] = NEGF;
    }
    // boundary slots: seq=-1
    for (int i = tid; i < (NCW - 1) * BRING; i += NT)
        ((float2*)bnd)[i] = make_float2(NEGF, __int_as_float(-1));
    __syncthreads();

    if (wid < NPW) {
        // ====================== PRODUCERS: stage log2 rows ======================
        const int pw = wid;
        const float4* __restrict__ ypv = (const float4*)yp;
        unsigned pstAddr  = su32(&pstage[pw]);
        unsigned progBase = su32(&prog[0]);

        int r = 1 + pw;                 // rows r, r+4, ..., <= 1023
        float4 v0 = __ldg(&ypv[(size_t)r * 32 + lane]);
        float4 v1 = __ldg(&ypv[(size_t)(r + 4) * 32 + lane]);
        float4 v2 = __ldg(&ypv[(size_t)(r + 8) * 32 + lane]);
        int slot = r;                    // r < RING initially
        int it = 0;
        for (; r <= Tc - 1; r += 4, ++it) {
            if ((it & 7) == 0) {
                // flow control: don't run > minprog + 48 (uniform, broadcast reads)
                for (;;) {
                    int m = ldsv32i(progBase);
                    #pragma unroll
                    for (int i = 1; i < NCW; ++i) m = min(m, ldsv32i(progBase + 4 * i));
                    if (r <= m + 48) break;
                    __nanosleep(128);
                }
            }
            float4 v = v0; v0 = v1; v1 = v2;
            int rn = r + 12;
            if (rn <= Tc - 1) v2 = __ldg(&ypv[(size_t)rn * 32 + lane]);
            float4 w;
            w.x = lg2f_(v.x + EPSF); w.y = lg2f_(v.y + EPSF);
            w.z = lg2f_(v.z + EPSF); w.w = lg2f_(v.w + EPSF);
            *(float4*)&lp[slot][lane * 4] = w;
            __threadfence_block();
            if (lane == 0) stsv32i(pstAddr, r);
            slot += 4; if (slot >= RING) slot -= RING;
        }
    } else {
        // ====================== CONSUMERS: alpha recurrence ======================
        const int  cw = wid - NPW;            // 0..7
        const int  p  = cw * 32 + lane;       // pair: states 2p (blank), 2p+1 (label yt[p])
        const bool hasPrevW = (cw > 0);
        const bool hasNextW = (cw < NCW - 1);
        const bool isA2lane = (cw == NCW - 1) && (lane == 31);

        const int  lab = yt[p];
        const bool skp = (p >= 1) && (lab != yt[p - 1]);
        const bool vE  = (2 * p     < Sval);
        const bool vL  = (2 * p + 1 < Sval);
        const bool v512 = (512 < Sval);

        unsigned bndPrev = hasPrevW ? su32(&bnd[cw - 1][0]) : 0u;
        unsigned bndOwn  = hasNextW ? su32(&bnd[cw][0])     : 0u;
        unsigned progOwn = su32(&prog[cw]);
        unsigned progNxt = hasNextW ? su32(&prog[cw + 1]) : 0u;
        unsigned pstBase = su32(&pstage[0]);

        float a0 = NEGF, a1 = NEGF, A2 = NEGF;
        if (p == 0) {
            a0 = lg2f_(yp[BLANKc] + EPSF);
            if (labLen > 0) a1 = lg2f_(yp[lab] + EPSF);
        }
        // initial boundary publish (seq = 0)
        if (hasNextW && lane == 31) stsv64(bndOwn, a1, __int_as_float(0));

        int slotT = 1;
        for (int t = 1; t <= Tc - 1; ++t) {
            // publish progress every 32 steps
            if (((t & 31) == 0) && lane == 0) stsv32i(progOwn, t);

            // row gate every 8 steps (uniform broadcast reads, uniform loop)
            if ((t & 7) == 1) {
                int target = min(t + 8, Tc - 1) - 3;
                for (;;) {
                    int m = ldsv32i(pstBase);
                    #pragma unroll
                    for (int i = 1; i < NPW; ++i) m = min(m, ldsv32i(pstBase + 4 * i));
                    if (m >= target) break;
                    __nanosleep(128);
                }
            }
            // boundary-writer throttle vs downstream reader (uniform)
            if (hasNextW && ((t & 7) == 0)) {
                while (t - ldsv32i(progNxt) > 48) __nanosleep(128);
            }
            // boundary read: all lanes load same slot (broadcast), uniform retry
            float h1b = NEGF;
            if (hasPrevW) {
                unsigned a = bndPrev + (unsigned)(((t - 1) & (BRING - 1)) << 3);
                float2 v = ldsv64(a);
                while (__float_as_int(v.y) != t - 1) { __nanosleep(64); v = ldsv64(a); }
                h1b = v.x;
            }
            float h1 = __shfl_up_sync(0xffffffffu, a1, 1);
            if (lane == 0) h1 = h1b;

            const float pb = lp[slotT][BLANKc];
            const float pl = lp[slotT][lab];
            const bool act = (t < inLen);

            float n0 = lse2f(a0, h1) + pb;
            float n1 = lse3f(a1, a0, skp ? h1 : NEGF) + pl;
            if (isA2lane) {
                float nA = lse2f(A2, a1) + pb;
                A2 = (act && v512) ? nA : A2;
            }
            a0 = (act && vE) ? n0 : a0;
            a1 = (act && vL) ? n1 : a1;

            if (hasNextW && lane == 31)
                stsv64(bndOwn + (unsigned)((t & (BRING - 1)) << 3), a1, __int_as_float(t));

            ++slotT; if (slotT >= RING) slotT = 0;
        }
        // release producers / writers
        if (lane == 0) stsv32i(progOwn, 1 << 20);

        // gather end states
        const int se = 2 * labLen;
        if (se < 512) { if (p == labLen) res2[0] = a0; }
        else          { if (isA2lane)    res2[0] = A2; }
        if (labLen > 0 && p == labLen - 1) res2[1] = a1;
    }

    __syncthreads();
    if (tid == 0) out[b] = -LN2F * lse2f(res2[0], res2[1]);
}

extern "C" void kernel_launch(void* const* d_in, const int* in_sizes, int n_in,
                              void* d_out, int out_size) {
    const int*   y_true       = (const int*)d_in[0];
    const float* y_pred       = (const float*)d_in[1];
    const int*   input_length = (const int*)d_in[2];
    const int*   label_length = (const int*)d_in[3];
    float* out = (float*)d_out;

    ctc_loss_kernel<<<Bc, NT>>>(y_true, y_pred, input_length, label_length, out);
}

// round 7
// speedup vs baseline: 2.5404x; 2.5404x over previous
#include <cuda_runtime.h>
#include <cstdint>

#define NEGF (-1e30f)
#define EPSF (1e-7f)
#define LN2F (0.69314718055994531f)

constexpr int Bc = 64;
constexpr int Tc = 1024;
constexpr int Cc = 128;
constexpr int Lc = 256;
constexpr int Sc = 2 * Lc + 1;   // 513
constexpr int BLANKc = Cc - 1;   // 127
constexpr int NT = 256;          // warps 0-3: forward group, warps 4-7: backward group
constexpr int NBF = 255;         // fwd 2-step blocks: t = 1..510, then single t=511
constexpr int NBB = 256;         // bwd 2-step blocks: t = 1023..512

#define BARF() asm volatile("bar.sync 1, 128;" ::: "memory")
#define BARB() asm volatile("bar.sync 2, 128;" ::: "memory")

__device__ __forceinline__ float ex2f_(float x){ float r; asm("ex2.approx.ftz.f32 %0, %1;" : "=f"(r) : "f"(x)); return r; }
__device__ __forceinline__ float lg2f_(float x){ float r; asm("lg2.approx.f32 %0, %1;"    : "=f"(r) : "f"(x)); return r; }

__device__ __forceinline__ float lse2f(float a, float b){
    float m = fmaxf(a, b), l = fminf(a, b);
    return m + lg2f_(1.0f + ex2f_(l - m));
}
__device__ __forceinline__ float lse3f(float x, float y, float z){
    float hi = fmaxf(x, y), lo = fminf(x, y);
    float m  = fmaxf(hi, z), t1 = fminf(hi, z);
    float mid = fmaxf(t1, lo), low = fminf(t1, lo);
    return m + lg2f_(1.0f + ex2f_(mid - m) + ex2f_(low - m));
}

__global__ __launch_bounds__(NT, 1) void ctc_loss_kernel(
    const int*   __restrict__ y_true,        // (B, L)
    const float* __restrict__ y_pred,        // (B, T, C)
    const int*   __restrict__ input_length,  // (B, 1)
    const int*   __restrict__ label_length,  // (B, 1)
    float*       __restrict__ out)           // (B, 1)
{
    __shared__ float  lpF[4][Cc];
    __shared__ float  lpG[4][Cc];
    __shared__ float4 haloF[2][130];   // [buf][tidF+2] = alpha[sb..sb+3]; [0],[1] sentinels
    __shared__ float4 haloG[2][129];   // [buf][tidG]   = gamma[sb..sb+3]; [128] sentinel
    __shared__ float  aSm[Sc];
    __shared__ float  gSm[Sc];
    __shared__ float  warpRes[4];

    const int b   = blockIdx.x;
    const int tid = threadIdx.x;
    const float* __restrict__ yp = y_pred + (size_t)b * Tc * Cc;
    const int*   __restrict__ yt = y_true + b * Lc;
    const int inLen  = input_length[b];
    const int labLen = label_length[b];
    const int Sval   = 2 * labLen + 1;

    if (tid < 128) {
        // =================== FORWARD GROUP (R2 core, t = 1..511) ===================
        const int ctid  = tid;
        const int sbase = ctid * 4;
        const bool own  = (sbase < Sval);
        const bool last = (ctid == 127);

        int  ext6[6]; bool skp6[6];
        #pragma unroll
        for (int k = 0; k < 6; ++k) { ext6[k] = BLANKc; skp6[k] = false; }
        #pragma unroll
        for (int k = 1; k < 6; k += 2) {
            int s = sbase - 2 + k;
            if (s >= 1 && s < Sc) {
                int j = s >> 1;
                ext6[k] = yt[j];
                if (s >= 3) skp6[k] = (ext6[k] != yt[j - 1]);
            }
        }

        float A0 = NEGF, A1 = NEGF, A2 = NEGF, A3 = NEGF, A4 = NEGF;
        if (ctid == 0) {
            A0 = lg2f_(yp[BLANKc] + EPSF);
            if (labLen > 0) A1 = lg2f_(yp[ext6[3]] + EPSF);   // ext6[3] = yt[0] at sbase=0
        }

        lpF[1][ctid] = lg2f_(yp[(size_t)1 * Cc + ctid] + EPSF);
        lpF[2][ctid] = lg2f_(yp[(size_t)2 * Cc + ctid] + EPSF);
        float pA0 = yp[(size_t)3 * Cc + ctid], pA1 = yp[(size_t)4 * Cc + ctid];
        float pB0 = yp[(size_t)5 * Cc + ctid], pB1 = yp[(size_t)6 * Cc + ctid];

        haloF[0][ctid + 2] = make_float4(A0, A1, A2, A3);
        if (ctid == 0) {
            float4 n4 = make_float4(NEGF, NEGF, NEGF, NEGF);
            haloF[0][0] = n4; haloF[0][1] = n4; haloF[1][0] = n4; haloF[1][1] = n4;
        }
        BARF();

        for (int j = 0; j < NBF; ++j) {
            const int t1 = 2 * j + 1, t2 = 2 * j + 2;
            lpF[(t1 + 2) & 3][ctid] = lg2f_(pA0 + EPSF);
            lpF[(t2 + 2) & 3][ctid] = lg2f_(pA1 + EPSF);
            pA0 = pB0; pA1 = pB1;
            pB0 = yp[(size_t)(2 * j + 7) * Cc + ctid];
            pB1 = yp[(size_t)(2 * j + 8) * Cc + ctid];

            if (own) {
                float4 hA = haloF[j & 1][ctid];
                float4 hB = haloF[j & 1][ctid + 1];
                float X[12];
                X[0]=hA.x; X[1]=hA.y; X[2]=hA.z; X[3]=hA.w;
                X[4]=hB.x; X[5]=hB.y; X[6]=hB.z; X[7]=hB.w;
                X[8]=A0;   X[9]=A1;   X[10]=A2;  X[11]=A3;

                const float* L1 = lpF[t1 & 3];
                const float* L2 = lpF[t2 & 3];
                const float lb1 = L1[BLANKc], lb2 = L2[BLANKc];
                const bool act1 = (t1 < inLen);
                const bool act2 = (t2 < inLen);

                // step t1: states s = sbase-2+k, k=0..5 (2 redundant), then 512
                float n[6];
                #pragma unroll
                for (int k = 0; k < 6; ++k) {
                    int s = sbase - 2 + k;
                    float v;
                    if ((k & 1) == 0) v = lse2f(X[k + 6], X[k + 5]);
                    else              v = lse3f(X[k + 6], X[k + 5], skp6[k] ? X[k + 4] : NEGF);
                    v += ((k & 1) == 0) ? lb1 : L1[ext6[k]];
                    v = ((unsigned)s < (unsigned)Sval) ? v : NEGF;
                    n[k] = act1 ? v : X[k + 6];
                }
                float n512 = A4;
                if (last) {
                    float v = lse2f(A4, X[11]) + lb1;
                    v = (512 < Sval) ? v : NEGF;
                    n512 = act1 ? v : A4;
                }
                // step t2: states sbase+k, k=0..3, then 512
                #pragma unroll
                for (int k = 0; k < 4; ++k) {
                    int s = sbase + k;
                    float v;
                    if ((k & 1) == 0) v = lse2f(n[k + 2], n[k + 1]);
                    else              v = lse3f(n[k + 2], n[k + 1], skp6[k + 2] ? n[k] : NEGF);
                    v += ((k & 1) == 0) ? lb2 : L2[ext6[k + 2]];
                    v = (s < Sval) ? v : NEGF;
                    float r = act2 ? v : n[k + 2];
                    if (k == 0) A0 = r; else if (k == 1) A1 = r;
                    else if (k == 2) A2 = r; else A3 = r;
                }
                if (last) {
                    float v = lse2f(n512, n[5]) + lb2;
                    v = (512 < Sval) ? v : NEGF;
                    A4 = act2 ? v : n512;
                }
            }
            haloF[(j + 1) & 1][ctid + 2] = make_float4(A0, A1, A2, A3);
            BARF();
        }

        // single step t = 511
        {
            const int t = 511;
            const float* Lf = lpF[t & 3];
            const float lbf = Lf[BLANKc];
            const bool act = (t < inLen);
            if (own) {
                float4 hB = haloF[NBF & 1][ctid + 1];
                float o[9];
                o[0]=hB.x; o[1]=hB.y; o[2]=hB.z; o[3]=hB.w;
                o[4]=A0; o[5]=A1; o[6]=A2; o[7]=A3; o[8]=A4;
                float r[5];
                #pragma unroll
                for (int k = 0; k < 4; ++k) {
                    int s = sbase + k;
                    float v;
                    if ((k & 1) == 0) v = lse2f(o[k + 4], o[k + 3]);
                    else              v = lse3f(o[k + 4], o[k + 3], skp6[k + 2] ? o[k + 2] : NEGF);
                    v += ((k & 1) == 0) ? lbf : Lf[ext6[k + 2]];
                    v = (s < Sval) ? v : NEGF;
                    r[k] = act ? v : o[k + 4];
                }
                r[4] = A4;
                if (last) {
                    float v = lse2f(o[8], o[7]) + lbf;
                    v = (512 < Sval) ? v : NEGF;
                    r[4] = act ? v : o[8];
                }
                A0 = r[0]; A1 = r[1]; A2 = r[2]; A3 = r[3]; A4 = r[4];
            }
        }
        aSm[sbase] = A0; aSm[sbase + 1] = A1; aSm[sbase + 2] = A2; aSm[sbase + 3] = A3;
        if (last) aSm[512] = A4;

    } else {
        // =================== BACKWARD GROUP (gamma, t = 1023..512) ===================
        const int tidG  = tid - 128;
        const int sbase = tidG * 4;
        const bool isLast = (tidG == 127);
        const int se = 2 * labLen;

        // e/skip tables for states s = sbase+k
        int  e8[8]; bool skb[6];
        #pragma unroll
        for (int k = 0; k < 8; ++k) {
            int s = sbase + k;
            e8[k] = (s & 1) ? yt[min(s >> 1, Lc - 1)] : BLANKc;
        }
        #pragma unroll
        for (int k = 0; k < 6; ++k) {
            int s = sbase + k;
            skb[k] = false;
            if ((s & 1) && s <= 509) {
                int j = s >> 1;
                skb[k] = (yt[j + 1] != yt[j]);
            }
        }

        // gamma init = end-state indicator (gamma_1024)
        float g0, g1, g2, g3, g4;
        g0 = (sbase     == se || (labLen > 0 && sbase     == se - 1)) ? 0.f : NEGF;
        g1 = (sbase + 1 == se || (labLen > 0 && sbase + 1 == se - 1)) ? 0.f : NEGF;
        g2 = (sbase + 2 == se || (labLen > 0 && sbase + 2 == se - 1)) ? 0.f : NEGF;
        g3 = (sbase + 3 == se || (labLen > 0 && sbase + 3 == se - 1)) ? 0.f : NEGF;
        g4 = (512 == se) ? 0.f : NEGF;

        lpG[3][tidG] = lg2f_(yp[(size_t)1023 * Cc + tidG] + EPSF);
        lpG[2][tidG] = lg2f_(yp[(size_t)1022 * Cc + tidG] + EPSF);
        float pA0 = yp[(size_t)1021 * Cc + tidG], pA1 = yp[(size_t)1020 * Cc + tidG];
        float pB0 = yp[(size_t)1019 * Cc + tidG], pB1 = yp[(size_t)1018 * Cc + tidG];

        haloG[0][tidG] = make_float4(g0, g1, g2, g3);
        if (tidG == 0) {
            float4 n4 = make_float4(NEGF, NEGF, NEGF, NEGF);
            haloG[0][128] = n4; haloG[1][128] = n4;
        }
        BARB();

        for (int j = 0; j < NBB; ++j) {
            const int t1 = 1023 - 2 * j, t2 = 1022 - 2 * j;
            lpG[(t1 - 2) & 3][tidG] = lg2f_(pA0 + EPSF);
            lpG[(t2 - 2) & 3][tidG] = lg2f_(pA1 + EPSF);
            pA0 = pB0; pA1 = pB1;
            {
                int r0 = max(t1 - 6, 0), r1 = max(t2 - 6, 0);
                pB0 = yp[(size_t)r0 * Cc + tidG];
                pB1 = yp[(size_t)r1 * Cc + tidG];
            }

            float4 H = haloG[j & 1][tidG + 1];
            if (isLast) H = make_float4(g4, NEGF, NEGF, NEGF);
            float G[8] = {g0, g1, g2, g3, H.x, H.y, H.z, H.w};

            const float* L1 = lpG[t1 & 3];
            const float* L2 = lpG[t2 & 3];
            const float lb1 = L1[BLANKc], lb2 = L2[BLANKc];
            const bool act1 = (t1 < inLen);
            const bool act2 = (t2 < inLen);

            // ---- step t1: states sbase..sbase+5 ----
            float D[8];
            D[0] = lb1 + G[0];       D[1] = L1[e8[1]] + G[1];
            D[2] = lb1 + G[2];       D[3] = L1[e8[3]] + G[3];
            D[4] = lb1 + G[4];       D[5] = L1[e8[5]] + G[5];
            D[6] = lb1 + G[6];       D[7] = L1[e8[7]] + G[7];
            float n[6];
            n[0] = lse2f(D[0], D[1]);
            n[1] = lse3f(D[1], D[2], skb[1] ? D[3] : NEGF);
            n[2] = lse2f(D[2], D[3]);
            n[3] = lse3f(D[3], D[4], skb[3] ? D[5] : NEGF);
            n[4] = lse2f(D[4], D[5]);
            n[5] = lse3f(D[5], D[6], skb[5] ? D[7] : NEGF);
            #pragma unroll
            for (int k = 0; k < 6; ++k) n[k] = act1 ? n[k] : G[k];
            float g4m = g4;
            if (isLast) g4m = act1 ? (lb1 + g4) : g4;

            // ---- step t2: states sbase..sbase+3 ----
            float E[6];
            E[0] = lb2 + n[0];       E[1] = L2[e8[1]] + n[1];
            E[2] = lb2 + n[2];       E[3] = L2[e8[3]] + n[3];
            E[4] = lb2 + n[4];       E[5] = L2[e8[5]] + n[5];
            float m0 = lse2f(E[0], E[1]);
            float m1 = lse3f(E[1], E[2], skb[1] ? E[3] : NEGF);
            float m2 = lse2f(E[2], E[3]);
            float m3 = lse3f(E[3], E[4], skb[3] ? E[5] : NEGF);
            g0 = act2 ? m0 : n[0];
            g1 = act2 ? m1 : n[1];
            g2 = act2 ? m2 : n[2];
            g3 = act2 ? m3 : n[3];
            if (isLast) g4 = act2 ? (lb2 + g4m) : g4m;

            haloG[(j + 1) & 1][tidG] = make_float4(g0, g1, g2, g3);
            BARB();
        }

        gSm[sbase] = g0; gSm[sbase + 1] = g1; gSm[sbase + 2] = g2; gSm[sbase + 3] = g3;
        if (isLast) gSm[512] = g4;
    }

    __syncthreads();

    // =================== COMBINE: loss = -ln2 * lse_s(alpha[s] + gamma[s]) ===================
    if (tid < 128) {
        const int s0 = tid * 4;
        float c0 = aSm[s0]     + gSm[s0];
        float c1 = aSm[s0 + 1] + gSm[s0 + 1];
        float c2 = aSm[s0 + 2] + gSm[s0 + 2];
        float c3 = aSm[s0 + 3] + gSm[s0 + 3];
        float local = lse2f(lse2f(c0, c1), lse2f(c2, c3));
        if (tid == 127) local = lse2f(local, aSm[512] + gSm[512]);
        #pragma unroll
        for (int off = 16; off > 0; off >>= 1)
            local = lse2f(local, __shfl_xor_sync(0xffffffffu, local, off));
        if ((tid & 31) == 0) warpRes[tid >> 5] = local;
        BARF();
        if (tid == 0) {
            float r = lse2f(lse2f(warpRes[0], warpRes[1]), lse2f(warpRes[2], warpRes[3]));
            out[b] = -LN2F * r;
        }
    }
}

extern "C" void kernel_launch(void* const* d_in, const int* in_sizes, int n_in,
                              void* d_out, int out_size) {
    const int*   y_true       = (const int*)d_in[0];
    const float* y_pred       = (const float*)d_in[1];
    const int*   input_length = (const int*)d_in[2];
    const int*   label_length = (const int*)d_in[3];
    float* out = (float*)d_out;

    ctc_loss_kernel<<<Bc, NT>>>(y_true, y_pred, input_length, label_length, out);
}

// round 8
// speedup vs baseline: 3.3797x; 1.3304x over previous
#include <cuda_runtime.h>
#include <cstdint>

#define NEGF (-1e30f)
#define EPSF (1e-7f)
#define LN2F (0.69314718055994531f)

constexpr int Bc = 64;
constexpr int Tc = 1024;
constexpr int Cc = 128;
constexpr int Lc = 256;
constexpr int Sc = 2 * Lc + 1;   // 513
constexpr int BLANKc = Cc - 1;   // 127
constexpr int NT = 128;
constexpr int NBF = 255;         // fwd 2-step blocks: t = 1..510, then single t=511
constexpr int NBB = 256;         // bwd 2-step blocks: t = 1023..512

__device__ float g_alpha[Bc][Sc];
__device__ float g_gamma[Bc][Sc];

__device__ __forceinline__ float ex2f_(float x){ float r; asm("ex2.approx.ftz.f32 %0, %1;" : "=f"(r) : "f"(x)); return r; }
__device__ __forceinline__ float lg2f_(float x){ float r; asm("lg2.approx.f32 %0, %1;"    : "=f"(r) : "f"(x)); return r; }

__device__ __forceinline__ float lse2f(float a, float b){
    float m = fmaxf(a, b), l = fminf(a, b);
    return m + lg2f_(1.0f + ex2f_(l - m));
}
__device__ __forceinline__ float lse3f(float x, float y, float z){
    float hi = fmaxf(x, y), lo = fminf(x, y);
    float m  = fmaxf(hi, z), t1 = fminf(hi, z);
    float mid = fmaxf(t1, lo), low = fminf(t1, lo);
    return m + lg2f_(1.0f + ex2f_(mid - m) + ex2f_(low - m));
}

__global__ __launch_bounds__(NT, 1) void ctc_fb_kernel(
    const int*   __restrict__ y_true,        // (B, L)
    const float* __restrict__ y_pred,        // (B, T, C)
    const int*   __restrict__ input_length,  // (B, 1)
    const int*   __restrict__ label_length)  // (B, 1)
{
    __shared__ float  lpS[4][Cc];
    __shared__ float4 halo[2][130];

    const bool fwd = (blockIdx.x < Bc);
    const int b    = fwd ? blockIdx.x : (blockIdx.x - Bc);
    const int tid  = threadIdx.x;
    const float* __restrict__ yp = y_pred + (size_t)b * Tc * Cc;
    const int*   __restrict__ yt = y_true + b * Lc;
    const int inLen  = input_length[b];
    const int labLen = label_length[b];
    const int Sval   = 2 * labLen + 1;

    if (fwd) {
        // =================== FORWARD (t = 1..511) ===================
        const int ctid  = tid;
        const int sbase = ctid * 4;
        const bool own  = (sbase < Sval);
        const bool last = (ctid == NT - 1);

        int  ext6[6]; bool skp6[6];
        #pragma unroll
        for (int k = 0; k < 6; ++k) { ext6[k] = BLANKc; skp6[k] = false; }
        #pragma unroll
        for (int k = 1; k < 6; k += 2) {
            int s = sbase - 2 + k;
            if (s >= 1 && s < Sc) {
                int j = s >> 1;
                ext6[k] = yt[j];
                if (s >= 3) skp6[k] = (ext6[k] != yt[j - 1]);
            }
        }

        float A0 = NEGF, A1 = NEGF, A2 = NEGF, A3 = NEGF, A4 = NEGF;
        if (ctid == 0) {
            A0 = lg2f_(yp[BLANKc] + EPSF);
            if (labLen > 0) A1 = lg2f_(yp[ext6[3]] + EPSF);
        }

        lpS[1][ctid] = lg2f_(yp[(size_t)1 * Cc + ctid] + EPSF);
        lpS[2][ctid] = lg2f_(yp[(size_t)2 * Cc + ctid] + EPSF);
        float pA0 = yp[(size_t)3 * Cc + ctid], pA1 = yp[(size_t)4 * Cc + ctid];
        float pB0 = yp[(size_t)5 * Cc + ctid], pB1 = yp[(size_t)6 * Cc + ctid];

        halo[0][ctid + 2] = make_float4(A0, A1, A2, A3);
        if (ctid == 0) {
            float4 n4 = make_float4(NEGF, NEGF, NEGF, NEGF);
            halo[0][0] = n4; halo[0][1] = n4; halo[1][0] = n4; halo[1][1] = n4;
        }
        __syncthreads();

        for (int j = 0; j < NBF; ++j) {
            const int t1 = 2 * j + 1, t2 = 2 * j + 2;
            lpS[(t1 + 2) & 3][ctid] = lg2f_(pA0 + EPSF);
            lpS[(t2 + 2) & 3][ctid] = lg2f_(pA1 + EPSF);
            pA0 = pB0; pA1 = pB1;
            pB0 = yp[(size_t)(2 * j + 7) * Cc + ctid];
            pB1 = yp[(size_t)(2 * j + 8) * Cc + ctid];

            if (own) {
                float4 hA = halo[j & 1][ctid];
                float4 hB = halo[j & 1][ctid + 1];
                float X[12];
                X[0]=hA.x; X[1]=hA.y; X[2]=hA.z; X[3]=hA.w;
                X[4]=hB.x; X[5]=hB.y; X[6]=hB.z; X[7]=hB.w;
                X[8]=A0;   X[9]=A1;   X[10]=A2;  X[11]=A3;

                const float* L1 = lpS[t1 & 3];
                const float* L2 = lpS[t2 & 3];
                const float lb1 = L1[BLANKc], lb2 = L2[BLANKc];
                const bool act1 = (t1 < inLen);
                const bool act2 = (t2 < inLen);

                float n[6];
                #pragma unroll
                for (int k = 0; k < 6; ++k) {
                    int s = sbase - 2 + k;
                    float v;
                    if ((k & 1) == 0) v = lse2f(X[k + 6], X[k + 5]);
                    else              v = lse3f(X[k + 6], X[k + 5], skp6[k] ? X[k + 4] : NEGF);
                    v += ((k & 1) == 0) ? lb1 : L1[ext6[k]];
                    v = ((unsigned)s < (unsigned)Sval) ? v : NEGF;
                    n[k] = act1 ? v : X[k + 6];
                }
                float n512 = A4;
                if (last) {
                    float v = lse2f(A4, X[11]) + lb1;
                    v = (512 < Sval) ? v : NEGF;
                    n512 = act1 ? v : A4;
                }
                #pragma unroll
                for (int k = 0; k < 4; ++k) {
                    int s = sbase + k;
                    float v;
                    if ((k & 1) == 0) v = lse2f(n[k + 2], n[k + 1]);
                    else              v = lse3f(n[k + 2], n[k + 1], skp6[k + 2] ? n[k] : NEGF);
                    v += ((k & 1) == 0) ? lb2 : L2[ext6[k + 2]];
                    v = (s < Sval) ? v : NEGF;
                    float r = act2 ? v : n[k + 2];
                    if (k == 0) A0 = r; else if (k == 1) A1 = r;
                    else if (k == 2) A2 = r; else A3 = r;
                }
                if (last) {
                    float v = lse2f(n512, n[5]) + lb2;
                    v = (512 < Sval) ? v : NEGF;
                    A4 = act2 ? v : n512;
                }
            }
            halo[(j + 1) & 1][ctid + 2] = make_float4(A0, A1, A2, A3);
            __syncthreads();
        }

        // single step t = 511
        {
            const int t = 511;
            const float* Lf = lpS[t & 3];
            const float lbf = Lf[BLANKc];
            const bool act = (t < inLen);
            if (own) {
                float4 hB = halo[NBF & 1][ctid + 1];
                float o[9];
                o[0]=hB.x; o[1]=hB.y; o[2]=hB.z; o[3]=hB.w;
                o[4]=A0; o[5]=A1; o[6]=A2; o[7]=A3; o[8]=A4;
                float r[5];
                #pragma unroll
                for (int k = 0; k < 4; ++k) {
                    int s = sbase + k;
                    float v;
                    if ((k & 1) == 0) v = lse2f(o[k + 4], o[k + 3]);
                    else              v = lse3f(o[k + 4], o[k + 3], skp6[k + 2] ? o[k + 2] : NEGF);
                    v += ((k & 1) == 0) ? lbf : Lf[ext6[k + 2]];
                    v = (s < Sval) ? v : NEGF;
                    r[k] = act ? v : o[k + 4];
                }
                r[4] = A4;
                if (last) {
                    float v = lse2f(o[8], o[7]) + lbf;
                    v = (512 < Sval) ? v : NEGF;
                    r[4] = act ? v : o[8];
                }
                A0 = r[0]; A1 = r[1]; A2 = r[2]; A3 = r[3]; A4 = r[4];
            }
        }
        float* __restrict__ aOut = g_alpha[b];
        aOut[sbase] = A0; aOut[sbase + 1] = A1; aOut[sbase + 2] = A2; aOut[sbase + 3] = A3;
        if (last) aOut[512] = A4;

    } else {
        // =================== BACKWARD (t = 1023..512) ===================
        const int tidG  = tid;
        const int sbase = tidG * 4;
        const bool isLast = (tidG == NT - 1);
        const int se = 2 * labLen;

        int  e8[8]; bool skb[6];
        #pragma unroll
        for (int k = 0; k < 8; ++k) {
            int s = sbase + k;
            e8[k] = (s & 1) ? yt[min(s >> 1, Lc - 1)] : BLANKc;
        }
        #pragma unroll
        for (int k = 0; k < 6; ++k) {
            int s = sbase + k;
            skb[k] = false;
            if ((s & 1) && s <= 509) {
                int j = s >> 1;
                skb[k] = (yt[j + 1] != yt[j]);
            }
        }

        float g0, g1, g2, g3, g4;
        g0 = (sbase     == se || (labLen > 0 && sbase     == se - 1)) ? 0.f : NEGF;
        g1 = (sbase + 1 == se || (labLen > 0 && sbase + 1 == se - 1)) ? 0.f : NEGF;
        g2 = (sbase + 2 == se || (labLen > 0 && sbase + 2 == se - 1)) ? 0.f : NEGF;
        g3 = (sbase + 3 == se || (labLen > 0 && sbase + 3 == se - 1)) ? 0.f : NEGF;
        g4 = (512 == se) ? 0.f : NEGF;

        lpS[3][tidG] = lg2f_(yp[(size_t)1023 * Cc + tidG] + EPSF);
        lpS[2][tidG] = lg2f_(yp[(size_t)1022 * Cc + tidG] + EPSF);
        float pA0 = yp[(size_t)1021 * Cc + tidG], pA1 = yp[(size_t)1020 * Cc + tidG];
        float pB0 = yp[(size_t)1019 * Cc + tidG], pB1 = yp[(size_t)1018 * Cc + tidG];

        halo[0][tidG] = make_float4(g0, g1, g2, g3);
        if (tidG == 0) {
            float4 n4 = make_float4(NEGF, NEGF, NEGF, NEGF);
            halo[0][128] = n4; halo[1][128] = n4;
        }
        __syncthreads();

        for (int j = 0; j < NBB; ++j) {
            const int t1 = 1023 - 2 * j, t2 = 1022 - 2 * j;
            lpS[(t1 - 2) & 3][tidG] = lg2f_(pA0 + EPSF);
            lpS[(t2 - 2) & 3][tidG] = lg2f_(pA1 + EPSF);
            pA0 = pB0; pA1 = pB1;
            {
                int r0 = max(t1 - 6, 0), r1 = max(t2 - 6, 0);
                pB0 = yp[(size_t)r0 * Cc + tidG];
                pB1 = yp[(size_t)r1 * Cc + tidG];
            }

            float4 H = halo[j & 1][tidG + 1];
            if (isLast) H = make_float4(g4, NEGF, NEGF, NEGF);
            float G[8] = {g0, g1, g2, g3, H.x, H.y, H.z, H.w};

            const float* L1 = lpS[t1 & 3];
            const float* L2 = lpS[t2 & 3];
            const float lb1 = L1[BLANKc], lb2 = L2[BLANKc];
            const bool act1 = (t1 < inLen);
            const bool act2 = (t2 < inLen);

            float D[8];
            D[0] = lb1 + G[0];       D[1] = L1[e8[1]] + G[1];
            D[2] = lb1 + G[2];       D[3] = L1[e8[3]] + G[3];
            D[4] = lb1 + G[4];       D[5] = L1[e8[5]] + G[5];
            D[6] = lb1 + G[6];       D[7] = L1[e8[7]] + G[7];
            float n[6];
            n[0] = lse2f(D[0], D[1]);
            n[1] = lse3f(D[1], D[2], skb[1] ? D[3] : NEGF);
            n[2] = lse2f(D[2], D[3]);
            n[3] = lse3f(D[3], D[4], skb[3] ? D[5] : NEGF);
            n[4] = lse2f(D[4], D[5]);
            n[5] = lse3f(D[5], D[6], skb[5] ? D[7] : NEGF);
            #pragma unroll
            for (int k = 0; k < 6; ++k) n[k] = act1 ? n[k] : G[k];
            float g4m = g4;
            if (isLast) g4m = act1 ? (lb1 + g4) : g4;

            float E[6];
            E[0] = lb2 + n[0];       E[1] = L2[e8[1]] + n[1];
            E[2] = lb2 + n[2];       E[3] = L2[e8[3]] + n[3];
            E[4] = lb2 + n[4];       E[5] = L2[e8[5]] + n[5];
            float m0 = lse2f(E[0], E[1]);
            float m1 = lse3f(E[1], E[2], skb[1] ? E[3] : NEGF);
            float m2 = lse2f(E[2], E[3]);
            float m3 = lse3f(E[3], E[4], skb[3] ? E[5] : NEGF);
            g0 = act2 ? m0 : n[0];
            g1 = act2 ? m1 : n[1];
            g2 = act2 ? m2 : n[2];
            g3 = act2 ? m3 : n[3];
            if (isLast) g4 = act2 ? (lb2 + g4m) : g4m;

            halo[(j + 1) & 1][tidG] = make_float4(g0, g1, g2, g3);
            __syncthreads();
        }

        float* __restrict__ gOut = g_gamma[b];
        gOut[sbase] = g0; gOut[sbase + 1] = g1; gOut[sbase + 2] = g2; gOut[sbase + 3] = g3;
        if (isLast) gOut[512] = g4;
    }
}

__global__ __launch_bounds__(NT, 1) void ctc_combine_kernel(float* __restrict__ out)
{
    __shared__ float warpRes[4];
    const int b   = blockIdx.x;
    const int tid = threadIdx.x;
    const float* __restrict__ a = g_alpha[b];
    const float* __restrict__ g = g_gamma[b];

    const int s0 = tid * 4;
    float c0 = a[s0]     + g[s0];
    float c1 = a[s0 + 1] + g[s0 + 1];
    float c2 = a[s0 + 2] + g[s0 + 2];
    float c3 = a[s0 + 3] + g[s0 + 3];
    float local = lse2f(lse2f(c0, c1), lse2f(c2, c3));
    if (tid == 127) local = lse2f(local, a[512] + g[512]);
    #pragma unroll
    for (int off = 16; off > 0; off >>= 1)
        local = lse2f(local, __shfl_xor_sync(0xffffffffu, local, off));
    if ((tid & 31) == 0) warpRes[tid >> 5] = local;
    __syncthreads();
    if (tid == 0) {
        float r = lse2f(lse2f(warpRes[0], warpRes[1]), lse2f(warpRes[2], warpRes[3]));
        out[b] = -LN2F * r;
    }
}

extern "C" void kernel_launch(void* const* d_in, const int* in_sizes, int n_in,
                              void* d_out, int out_size) {
    const int*   y_true       = (const int*)d_in[0];
    const float* y_pred       = (const float*)d_in[1];
    const int*   input_length = (const int*)d_in[2];
    const int*   label_length = (const int*)d_in[3];
    float* out = (float*)d_out;

    ctc_fb_kernel<<<2 * Bc, NT>>>(y_true, y_pred, input_length, label_length);
    ctc_combine_kernel<<<Bc, NT>>>(out);
}